// round 1
// baseline (speedup 1.0000x reference)
#include <cuda_runtime.h>
#include <math.h>

// Problem constants
#define BB 128
#define RR 4608
#define KKK 2
#define OO 32
#define II 16
#define KO 64          // K*O
#define INV_B (1.0f/128.0f)
#define INV_R (1.0f/4608.0f)

// Scratch (static device arrays; no allocation in kernel_launch)
__device__ float g_uhat[(size_t)RR * BB * KO];  // layout [r][b][k*32+o], ~151 MB
__device__ float g_s0[BB * KO];                 // raw sum over r of u_hat
__device__ float g_S[2][BB * KO];               // unnormalized weighted sums (pass 0, 1)
__device__ float g_Z[2][KKK];                   // softmax denominators
__device__ float g_v[2][BB * KO];               // v0, v1
__device__ float g_b1[RR * KKK];                // b_ij after iteration 0

// ---------------------------------------------------------------------------
// Zero accumulators (must run each call: graph replays reuse device state)
// ---------------------------------------------------------------------------
__global__ void zero_kernel() {
    int t = blockIdx.x * blockDim.x + threadIdx.x;   // 8192 threads
    g_s0[t]   = 0.f;
    g_S[0][t] = 0.f;
    g_S[1][t] = 0.f;
    if (t < 2 * KKK) ((float*)g_Z)[t] = 0.f;
}

// ---------------------------------------------------------------------------
// K1: u_hat[b,r,k,o] = sum_i W[r,k,o,i] * x[b,r,i]; also accumulate
//     s0_raw[b,ko] = sum_r u_hat (iter-0 softmax of zeros is uniform 1/R).
// CTA: 256 threads = (128 b) x (2 halves of ko); 32 r per CTA -> 144 CTAs.
// ---------------------------------------------------------------------------
__global__ __launch_bounds__(256) void gemm_kernel(const float* __restrict__ x,
                                                   const float* __restrict__ W) {
    __shared__ float sW[KO * II];    // 4 KB: W[r] tile
    const int tid  = threadIdx.x;
    const int b    = tid >> 1;
    const int half = tid & 1;        // half == k

    float acc[32];
    #pragma unroll
    for (int j = 0; j < 32; j++) acc[j] = 0.f;

    const int r0 = blockIdx.x * 32;
    for (int rr = 0; rr < 32; ++rr) {
        const int r = r0 + rr;
        __syncthreads();   // protect sW from previous iteration's readers
        ((float4*)sW)[tid] = ((const float4*)(W + (size_t)r * 1024))[tid];
        __syncthreads();

        const float4* xp = (const float4*)(x + ((size_t)b * RR + r) * II);
        const float4 xa = xp[0], xb = xp[1], xc = xp[2], xd = xp[3];

        float4* up = (float4*)(g_uhat + ((size_t)r * BB + b) * KO + half * 32);
        #pragma unroll
        for (int j4 = 0; j4 < 8; j4++) {
            float4 ov;
            float* o = (float*)&ov;
            #pragma unroll
            for (int jj = 0; jj < 4; jj++) {
                const int j = j4 * 4 + jj;
                const float4* wr = (const float4*)(sW + (half * 32 + j) * II);
                const float4 w0 = wr[0], w1 = wr[1], w2 = wr[2], w3 = wr[3];
                float s;
                s  = xa.x * w0.x; s += xa.y * w0.y; s += xa.z * w0.z; s += xa.w * w0.w;
                s += xb.x * w1.x; s += xb.y * w1.y; s += xb.z * w1.z; s += xb.w * w1.w;
                s += xc.x * w2.x; s += xc.y * w2.y; s += xc.z * w2.z; s += xc.w * w2.w;
                s += xd.x * w3.x; s += xd.y * w3.y; s += xd.z * w3.z; s += xd.w * w3.w;
                o[jj] = s;
                acc[j] += s;
            }
            up[j4] = ov;
        }
    }

    float* sp = g_s0 + b * KO + half * 32;
    #pragma unroll
    for (int j = 0; j < 32; j++) atomicAdd(&sp[j], acc[j]);
}

// ---------------------------------------------------------------------------
// Squash: one warp per (b,k) capsule; lane = o.
// mode 0: v0 = squash(s0_raw / R)         -> g_v[0]
// mode 1: v1 = squash(S[0]/Z[0])          -> g_v[1]
// mode 2: out = squash(S[1]/Z[1])         -> d_out
// squash(s) = s * sqrt(sn) / (0.5 + sn),  sn = ||s||^2 over O
// ---------------------------------------------------------------------------
__global__ void squash_kernel(int mode, float* __restrict__ out) {
    const int t = blockIdx.x * blockDim.x + threadIdx.x;  // 8192
    const int k = (t >> 5) & 1;
    float s;
    if (mode == 0) {
        s = g_s0[t] * INV_R;
    } else {
        const int p = mode - 1;
        s = g_S[p][t] / g_Z[p][k];
    }
    float sq = s * s;
    #pragma unroll
    for (int m = 16; m >= 1; m >>= 1) sq += __shfl_xor_sync(0xffffffffu, sq, m);
    const float sn = sq;
    const float f = sqrtf(sn) / (0.5f + sn);
    const float v = s * f;
    if (mode == 2) out[t] = v;
    else           g_v[mode][t] = v;
}

// ---------------------------------------------------------------------------
// Fused routing pass (agreement for iter t + weighted sum for iter t+1).
// For each r (all per-r local thanks to deferred softmax normalization):
//   a[r,k]  = (1/B) sum_{b,o} u_hat[b,r,k,o] * v[b,k,o]
//   bnew    = bprev[r,k] + a[r,k]
//   e       = exp(bnew)
//   Z[k]   += e ;  S[b,k,o] += e * u_hat[b,r,k,o]
// CTA: 256 threads = (128 b) x (2 k); 16 r per CTA -> 288 CTAs.
// pass 0: v = g_v[0], bprev = 0, store b1;  pass 1: v = g_v[1], bprev = g_b1.
// ---------------------------------------------------------------------------
__global__ __launch_bounds__(256, 2) void routing_kernel(int pass) {
    __shared__ float red[16];
    __shared__ float ebc[2];
    const int tid  = threadIdx.x;
    const int lane = tid & 31;
    const int warp = tid >> 5;
    const int b    = tid >> 1;
    const int k    = tid & 1;

    const float* __restrict__ vin = g_v[pass];
    float* __restrict__ Sout = g_S[pass];
    float* __restrict__ Zout = g_Z[pass];

    float vv[32];
    const float4* vp = (const float4*)(vin + b * KO + k * 32);
    #pragma unroll
    for (int j = 0; j < 8; j++) ((float4*)vv)[j] = vp[j];

    float Sacc[32];
    #pragma unroll
    for (int j = 0; j < 32; j++) Sacc[j] = 0.f;
    float zacc = 0.f;

    const int r0 = blockIdx.x * 16;
    for (int rr = 0; rr < 16; ++rr) {
        const int r = r0 + rr;
        const float4* up = (const float4*)(g_uhat + ((size_t)r * BB + b) * KO + k * 32);
        float u[32];
        #pragma unroll
        for (int j = 0; j < 8; j++) ((float4*)u)[j] = up[j];

        float dot = 0.f;
        #pragma unroll
        for (int o = 0; o < 32; o++) dot += u[o] * vv[o];
        // reduce over the 16 b-values in this warp, keeping k (lane bit 0)
        #pragma unroll
        for (int m = 16; m >= 2; m >>= 1) dot += __shfl_xor_sync(0xffffffffu, dot, m);
        if (lane < 2) red[warp * 2 + lane] = dot;
        __syncthreads();
        if (tid < 2) {  // tid == k
            float a = 0.f;
            #pragma unroll
            for (int w = 0; w < 8; w++) a += red[w * 2 + tid];
            a *= INV_B;
            float bn = a;
            if (pass == 1) bn += g_b1[(size_t)r * KKK + tid];
            else           g_b1[(size_t)r * KKK + tid] = bn;
            ebc[tid] = expf(bn);
        }
        __syncthreads();
        const float e = ebc[k];
        if (tid < 2) zacc += e;
        #pragma unroll
        for (int o = 0; o < 32; o++) Sacc[o] += e * u[o];
        // no trailing sync needed: next red-write happens only after the
        // barrier above, which orders it after all ebc reads of this iter
    }

    float* sp = Sout + b * KO + k * 32;
    #pragma unroll
    for (int o = 0; o < 32; o++) atomicAdd(&sp[o], Sacc[o]);
    if (tid < 2) atomicAdd(&Zout[tid], zacc);
}

// ---------------------------------------------------------------------------
extern "C" void kernel_launch(void* const* d_in, const int* in_sizes, int n_in,
                              void* d_out, int out_size) {
    const float* x = (const float*)d_in[0];   // [128, 4608, 16]
    const float* W = (const float*)d_in[1];   // [1, 4608, 2, 32, 16]
    float* out = (float*)d_out;               // [128, 2, 32]

    zero_kernel<<<32, 256>>>();
    gemm_kernel<<<RR / 32, 256>>>(x, W);          // u_hat + s0 sum
    squash_kernel<<<32, 256>>>(0, nullptr);       // v0
    routing_kernel<<<RR / 16, 256>>>(0);          // a0 -> b1 -> S1, Z1
    squash_kernel<<<32, 256>>>(1, nullptr);       // v1
    routing_kernel<<<RR / 16, 256>>>(1);          // a1 -> b2 -> S2, Z2
    squash_kernel<<<32, 256>>>(2, out);           // v2 -> output
}